// round 9
// baseline (speedup 1.0000x reference)
#include <cuda_runtime.h>
#include <cstdint>

#define N_PTS   400000
#define NXY     468
#define CANVAS  (468 * 468)          // 219024
#define VXY     0.32f
#define VZf     6.0f
#define PCMINX  (-74.88f)
#define PCMINY  (-74.88f)
#define PCMINZ  (-2.0f)

// -------- scratch (static device globals; no allocations allowed) ----------
__device__ int   g_flat[N_PTS];
__device__ int   g_cnt[CANVAS];
__device__ float g_vsum[CANVAS * 3];
__device__ float g_v1[CANVAS * 64];             // 56 MB
__device__ float g_pf1[(size_t)N_PTS * 64];     // 102 MB row-major [pt][64]

// packed f32x2 FMA (Blackwell FFMA2) — d = a*b + d on 2 packed fp32
__device__ __forceinline__ void fma2(uint64_t& d, uint64_t a, uint64_t b) {
    asm("fma.rn.f32x2 %0, %1, %2, %0;" : "+l"(d) : "l"(a), "l"(b));
}

// ---------------------------------------------------------------------------
// K0: zero cnt / vsum / v1 / out
// ---------------------------------------------------------------------------
__global__ void k_init(float* __restrict__ out) {
    int idx = blockIdx.x * blockDim.x + threadIdx.x;
    int stride = gridDim.x * blockDim.x;
    const int n4 = (CANVAS * 64) / 4;
    float4 z = make_float4(0.f, 0.f, 0.f, 0.f);
    float4* o4 = (float4*)out;
    float4* v4 = (float4*)g_v1;
    for (int i = idx; i < n4; i += stride) {
        o4[i] = z;
        v4[i] = z;
    }
    for (int i = idx; i < CANVAS; i += stride) {
        g_cnt[i] = 0;
        g_vsum[3 * i + 0] = 0.f;
        g_vsum[3 * i + 1] = 0.f;
        g_vsum[3 * i + 2] = 0.f;
    }
}

// ---------------------------------------------------------------------------
// K1: per-point voxel index + count / xyz-sum scatter
// ---------------------------------------------------------------------------
__device__ __forceinline__ int voxel_coord(float v, float vmin, float vox, int nmax) {
    int c = (int)floorf(__fdiv_rn(v - vmin, vox));
    return min(max(c, 0), nmax - 1);
}

__global__ void k_scatter(const float* __restrict__ pts) {
    int i = blockIdx.x * blockDim.x + threadIdx.x;
    if (i >= N_PTS) return;
    float x = pts[i * 5 + 0];
    float y = pts[i * 5 + 1];
    float z = pts[i * 5 + 2];
    int cx = voxel_coord(x, PCMINX, VXY, NXY);
    int cy = voxel_coord(y, PCMINY, VXY, NXY);
    int flat = cy * NXY + cx;          // NZ==1 -> cz always 0
    g_flat[i] = flat;
    atomicAdd(&g_cnt[flat], 1);
    atomicAdd(&g_vsum[3 * flat + 0], x);
    atomicAdd(&g_vsum[3 * flat + 1], y);
    atomicAdd(&g_vsum[3 * flat + 2], z);
}

// ---------------------------------------------------------------------------
// K2: pf1 = relu(features @ W1); store g_pf1 row-major, atomicMax into v1.
// warp per point; lane -> channels (lane, lane+32).  (proven shape)
// ---------------------------------------------------------------------------
__global__ void k_pf1(const float* __restrict__ pts, const float* __restrict__ W1) {
    __shared__ float sW1[11 * 64];
    int tid = threadIdx.x;
    for (int i = tid; i < 11 * 64; i += 256) sW1[i] = W1[i];
    __syncthreads();

    int warp = tid >> 5;
    int lane = tid & 31;
    int i = blockIdx.x * 8 + warp;
    if (i >= N_PTS) return;

    float x  = pts[i * 5 + 0];
    float y  = pts[i * 5 + 1];
    float z  = pts[i * 5 + 2];
    float p3 = pts[i * 5 + 3];
    float p4 = pts[i * 5 + 4];

    int flat = g_flat[i];
    float inv = 1.0f / fmaxf((float)g_cnt[flat], 1.0f);
    float mx = g_vsum[3 * flat + 0] * inv;
    float my = g_vsum[3 * flat + 1] * inv;
    float mz = g_vsum[3 * flat + 2] * inv;

    int cxv = flat % NXY;
    int cyv = flat / NXY;

    float f[11];
    f[0] = x;  f[1] = y;  f[2] = z;  f[3] = p3;  f[4] = p4;
    f[5] = x - mx;  f[6] = y - my;  f[7] = z - mz;
    f[8]  = x - ((float)cxv * VXY + (VXY * 0.5f + PCMINX));
    f[9]  = y - ((float)cyv * VXY + (VXY * 0.5f + PCMINY));
    f[10] = z - (VZf * 0.5f + PCMINZ);

    float a0 = 0.f, a1 = 0.f;
    #pragma unroll
    for (int k = 0; k < 11; k++) {
        a0 = fmaf(f[k], sW1[k * 64 + lane], a0);
        a1 = fmaf(f[k], sW1[k * 64 + lane + 32], a1);
    }
    a0 = fmaxf(a0, 0.f);
    a1 = fmaxf(a1, 0.f);

    g_pf1[(size_t)i * 64 + lane]      = a0;
    g_pf1[(size_t)i * 64 + lane + 32] = a1;

    // relu >= 0 and v1 zero-initialized -> int atomicMax reproduces
    // where(occ, segment_max, 0) exactly.
    if (a0 > 0.f) atomicMax((int*)&g_v1[(size_t)flat * 64 + lane],      __float_as_int(a0));
    if (a1 > 0.f) atomicMax((int*)&g_v1[(size_t)flat * 64 + lane + 32], __float_as_int(a1));
}

// ---------------------------------------------------------------------------
// K3: pf2 = relu([pf1, v1[flat]] @ W2), scatter-max into out.
// Tile 64 pts x 64 cols, 256 threads; thread = 2 pts x 8 cols with f32x2
// accumulators over COLUMN pairs:
//   A stored duplicated {a,a} in smem (sAd[k][pt] u64) -> 1 LDS.128 / k-step
//   B stored as natural col-pairs, instr-interleaved     -> 2 LDS.128 / k-step
//   8 fma2 (16 FMA) per k-step. All LDS conflict-free.
// ---------------------------------------------------------------------------
#define BP      64
#define SA_LD   132                          // words per k-row of A (pad 4)
#define SA_WORDS (64 * SA_LD)                // 8448
#define SB_WORDS (64 * 64)                   // 4096
#define SMEM_BYTES ((SA_WORDS + SB_WORDS) * 4)   // 50176

// B word offset for column c within a k-row:
//  instr0 region words [0,32): cols with (c&4)==0 ; instr1 region [32,64)
__device__ __forceinline__ int b_word(int c) {
    return ((c & 4) << 3) + ((c >> 3) << 2) + (c & 3);
}

__global__ __launch_bounds__(256, 4)
void k_pf2(const float* __restrict__ W2, float* __restrict__ out) {
    extern __shared__ float smem[];
    float* sAd = smem;                       // [64 k][SA_LD] (u64 dup pairs)
    float* sB  = smem + SA_WORDS;            // [64 k][64]    (col pairs)

    int tid = threadIdx.x;
    int p0  = blockIdx.x * BP;               // 6250 * 64 = 400000 exactly
    int ty  = tid >> 3;                      // 0..31 -> pts ty*2, ty*2+1
    int cx  = tid & 7;                       // 0..7  -> cols cx*8 .. +7

    uint64_t acc[2][4];                      // [pt][colpair]
    #pragma unroll
    for (int p = 0; p < 2; p++)
        #pragma unroll
        for (int j = 0; j < 4; j++) acc[p][j] = 0ull;

    #pragma unroll 1
    for (int chunk = 0; chunk < 2; chunk++) {
        if (chunk) __syncthreads();

        // ---- stage B chunk (no dup): col c -> word k*64 + b_word(c)
        for (int i = tid; i < 4096; i += 256) {
            int k = i >> 6, c = i & 63;
            sB[k * 64 + b_word(c)] = W2[(chunk * 64 + k) * 64 + c];
        }

        // ---- stage A duplicated: sAd[k][pt] = {a,a}
        for (int i = tid; i < 1024; i += 256) {
            int pt = i >> 4, q = i & 15;     // q = float4 index along k
            const float4* src;
            if (chunk == 0) {
                src = (const float4*)(g_pf1 + (size_t)(p0 + pt) * 64);
            } else {
                src = (const float4*)(g_v1 + (size_t)g_flat[p0 + pt] * 64);
            }
            float4 v = src[q];
            float vv[4] = {v.x, v.y, v.z, v.w};
            #pragma unroll
            for (int j = 0; j < 4; j++) {
                float2* d = (float2*)&sAd[(q * 4 + j) * SA_LD + pt * 2];
                *d = make_float2(vv[j], vv[j]);
            }
        }
        __syncthreads();

        // ---- mainloop: 64 rank-1 updates
        const float* aptr = sAd + ty * 4;    // words k*SA_LD + 4ty
        const float* bptr = sB + cx * 4;     // words k*64 + {0,32} + 4cx
        #pragma unroll 8
        for (int k = 0; k < 64; k++) {
            ulonglong2 ua = *(const ulonglong2*)(aptr + k * SA_LD);
            //  ua.x = {a(2ty), a(2ty)},  ua.y = {a(2ty+1), a(2ty+1)}
            ulonglong2 b0 = *(const ulonglong2*)(bptr + k * 64);       // cp 4cx,4cx+1
            ulonglong2 b1 = *(const ulonglong2*)(bptr + k * 64 + 32);  // cp 4cx+2,4cx+3

            fma2(acc[0][0], ua.x, b0.x); fma2(acc[0][1], ua.x, b0.y);
            fma2(acc[0][2], ua.x, b1.x); fma2(acc[0][3], ua.x, b1.y);
            fma2(acc[1][0], ua.y, b0.x); fma2(acc[1][1], ua.y, b0.y);
            fma2(acc[1][2], ua.y, b1.x); fma2(acc[1][3], ua.y, b1.y);
        }
    }

    // ---- epilogue: relu + guarded scatter atomicMax (out pre-zeroed)
    #pragma unroll
    for (int p = 0; p < 2; p++) {
        int gp = p0 + ty * 2 + p;
        int fl = g_flat[gp];
        int* o = (int*)(out + (size_t)fl * 64 + cx * 8);
        #pragma unroll
        for (int j = 0; j < 4; j++) {
            float lo = __uint_as_float((uint32_t)(acc[p][j] & 0xffffffffu));
            float hi = __uint_as_float((uint32_t)(acc[p][j] >> 32));
            if (lo > 0.f) atomicMax(o + 2 * j,     __float_as_int(lo));
            if (hi > 0.f) atomicMax(o + 2 * j + 1, __float_as_int(hi));
        }
    }
}

// ---------------------------------------------------------------------------
extern "C" void kernel_launch(void* const* d_in, const int* in_sizes, int n_in,
                              void* d_out, int out_size) {
    const float* points = (const float*)d_in[0];  // [400000, 5]
    const float* W1     = (const float*)d_in[1];  // [11, 64]
    const float* W2     = (const float*)d_in[2];  // [128, 64]
    float* out = (float*)d_out;                   // [219024, 64]

    cudaFuncSetAttribute(k_pf2, cudaFuncAttributeMaxDynamicSharedMemorySize,
                         SMEM_BYTES);

    k_init<<<8192, 256>>>(out);
    k_scatter<<<(N_PTS + 255) / 256, 256>>>(points);
    k_pf1<<<N_PTS / 8, 256>>>(points, W1);
    k_pf2<<<N_PTS / BP, 256, SMEM_BYTES>>>(W2, out);
}

// round 10
// speedup vs baseline: 1.3904x; 1.3904x over previous
#include <cuda_runtime.h>
#include <cstdint>

#define N_PTS   400000
#define NXY     468
#define CANVAS  (468 * 468)          // 219024
#define VXY     0.32f
#define VZf     6.0f
#define PCMINX  (-74.88f)
#define PCMINY  (-74.88f)
#define PCMINZ  (-2.0f)

// -------- scratch (static device globals; no allocations allowed) ----------
__device__ int   g_flat[N_PTS];
__device__ int   g_cnt[CANVAS];
__device__ float g_vsum[CANVAS * 3];
__device__ float g_v1[CANVAS * 64];             // 56 MB
__device__ float g_pf1[(size_t)N_PTS * 64];     // 102 MB row-major [pt][64]
__device__ float g_M[CANVAS * 64];              // 56 MB  pre-relu segment max

#define NEG_INF_BITS 0xff800000u

// ---------------------------------------------------------------------------
// K0: zero cnt / vsum / v1 ; fill M with -inf.  (out is written densely later)
// ---------------------------------------------------------------------------
__global__ void k_init() {
    int idx = blockIdx.x * blockDim.x + threadIdx.x;
    int stride = gridDim.x * blockDim.x;
    const int n4 = (CANVAS * 64) / 4;
    float4 z = make_float4(0.f, 0.f, 0.f, 0.f);
    float ninf = __uint_as_float(NEG_INF_BITS);
    float4 nf = make_float4(ninf, ninf, ninf, ninf);
    float4* v4 = (float4*)g_v1;
    float4* m4 = (float4*)g_M;
    for (int i = idx; i < n4; i += stride) {
        v4[i] = z;
        m4[i] = nf;
    }
    for (int i = idx; i < CANVAS; i += stride) {
        g_cnt[i] = 0;
        g_vsum[3 * i + 0] = 0.f;
        g_vsum[3 * i + 1] = 0.f;
        g_vsum[3 * i + 2] = 0.f;
    }
}

// ---------------------------------------------------------------------------
// K1: per-point voxel index + count / xyz-sum scatter
// ---------------------------------------------------------------------------
__device__ __forceinline__ int voxel_coord(float v, float vmin, float vox, int nmax) {
    int c = (int)floorf(__fdiv_rn(v - vmin, vox));
    return min(max(c, 0), nmax - 1);
}

__global__ void k_scatter(const float* __restrict__ pts) {
    int i = blockIdx.x * blockDim.x + threadIdx.x;
    if (i >= N_PTS) return;
    float x = pts[i * 5 + 0];
    float y = pts[i * 5 + 1];
    float z = pts[i * 5 + 2];
    int cx = voxel_coord(x, PCMINX, VXY, NXY);
    int cy = voxel_coord(y, PCMINY, VXY, NXY);
    int flat = cy * NXY + cx;          // NZ==1 -> cz always 0
    g_flat[i] = flat;
    atomicAdd(&g_cnt[flat], 1);
    atomicAdd(&g_vsum[3 * flat + 0], x);
    atomicAdd(&g_vsum[3 * flat + 1], y);
    atomicAdd(&g_vsum[3 * flat + 2], z);
}

// ---------------------------------------------------------------------------
// K2: pf1 = relu(features @ W1); store g_pf1 row-major, atomicMax into v1.
// warp per point; lane -> channels (lane, lane+32).  (R1-proven shape)
// relu >= 0 and v1 zero-init -> int atomicMax is exact.
// ---------------------------------------------------------------------------
__global__ void k_pf1(const float* __restrict__ pts, const float* __restrict__ W1) {
    __shared__ float sW1[11 * 64];
    int tid = threadIdx.x;
    for (int i = tid; i < 11 * 64; i += 256) sW1[i] = W1[i];
    __syncthreads();

    int warp = tid >> 5;
    int lane = tid & 31;
    int i = blockIdx.x * 8 + warp;
    if (i >= N_PTS) return;

    float x  = pts[i * 5 + 0];
    float y  = pts[i * 5 + 1];
    float z  = pts[i * 5 + 2];
    float p3 = pts[i * 5 + 3];
    float p4 = pts[i * 5 + 4];

    int flat = g_flat[i];
    float inv = 1.0f / fmaxf((float)g_cnt[flat], 1.0f);
    float mx = g_vsum[3 * flat + 0] * inv;
    float my = g_vsum[3 * flat + 1] * inv;
    float mz = g_vsum[3 * flat + 2] * inv;

    int cxv = flat % NXY;
    int cyv = flat / NXY;

    float f[11];
    f[0] = x;  f[1] = y;  f[2] = z;  f[3] = p3;  f[4] = p4;
    f[5] = x - mx;  f[6] = y - my;  f[7] = z - mz;
    f[8]  = x - ((float)cxv * VXY + (VXY * 0.5f + PCMINX));
    f[9]  = y - ((float)cyv * VXY + (VXY * 0.5f + PCMINY));
    f[10] = z - (VZf * 0.5f + PCMINZ);

    float a0 = 0.f, a1 = 0.f;
    #pragma unroll
    for (int k = 0; k < 11; k++) {
        a0 = fmaf(f[k], sW1[k * 64 + lane], a0);
        a1 = fmaf(f[k], sW1[k * 64 + lane + 32], a1);
    }
    a0 = fmaxf(a0, 0.f);
    a1 = fmaxf(a1, 0.f);

    g_pf1[(size_t)i * 64 + lane]      = a0;
    g_pf1[(size_t)i * 64 + lane + 32] = a1;

    if (a0 > 0.f) atomicMax((int*)&g_v1[(size_t)flat * 64 + lane],      __float_as_int(a0));
    if (a1 > 0.f) atomicMax((int*)&g_v1[(size_t)flat * 64 + lane + 32], __float_as_int(a1));
}

// ---------------------------------------------------------------------------
// float atomic max supporting negatives:
// sign>=0 -> int atomicMax; sign<0 -> uint atomicMin.  Init -inf.
// Orderings commute; result is the true float max.
// ---------------------------------------------------------------------------
__device__ __forceinline__ void atomicMaxFloat(float* addr, float v) {
    int b = __float_as_int(v);
    if (b >= 0) atomicMax((int*)addr, b);
    else        atomicMin((unsigned int*)addr, (unsigned int)b);
}

// ===========================================================================
// R1-proven GEMM microkernel shape: 64 rows x 64 cols tile, 256 threads,
// 4x4 register tile, K=64.  sW [64][64], sA [64][68].
// ===========================================================================
#define SA_LD 68

// ---------------------------------------------------------------------------
// K3: s = pf1 @ W2[:64]  (pre-relu), scatter atomicMaxFloat into M[flat].
// ---------------------------------------------------------------------------
__global__ __launch_bounds__(256)
void k_pf2a(const float* __restrict__ W2) {
    __shared__ float sW[64 * 64];
    __shared__ float sA[64 * SA_LD];

    int tid = threadIdx.x;
    int p0 = blockIdx.x * 64;          // 6250 * 64 = 400000 exactly
    int tx = tid & 15;
    int ty = tid >> 4;

    float acc[4][4];
    #pragma unroll
    for (int r = 0; r < 4; r++)
        #pragma unroll
        for (int c = 0; c < 4; c++) acc[r][c] = 0.f;

    for (int i = tid; i < 4096; i += 256) sW[i] = W2[i];   // W2 rows 0..63
    {
        int r = tid >> 2, q = tid & 3;
        const float4* src = (const float4*)(g_pf1 + (size_t)(p0 + r) * 64);
        #pragma unroll
        for (int i = 0; i < 4; i++) {
            float4 v = src[q * 4 + i];
            *(float4*)&sA[r * SA_LD + (q * 4 + i) * 4] = v;
        }
    }
    __syncthreads();

    #pragma unroll 16
    for (int k = 0; k < 64; k++) {
        float4 b = *(const float4*)&sW[k * 64 + tx * 4];
        float a0 = sA[(ty * 4 + 0) * SA_LD + k];
        float a1 = sA[(ty * 4 + 1) * SA_LD + k];
        float a2 = sA[(ty * 4 + 2) * SA_LD + k];
        float a3 = sA[(ty * 4 + 3) * SA_LD + k];
        acc[0][0] = fmaf(a0, b.x, acc[0][0]); acc[0][1] = fmaf(a0, b.y, acc[0][1]);
        acc[0][2] = fmaf(a0, b.z, acc[0][2]); acc[0][3] = fmaf(a0, b.w, acc[0][3]);
        acc[1][0] = fmaf(a1, b.x, acc[1][0]); acc[1][1] = fmaf(a1, b.y, acc[1][1]);
        acc[1][2] = fmaf(a1, b.z, acc[1][2]); acc[1][3] = fmaf(a1, b.w, acc[1][3]);
        acc[2][0] = fmaf(a2, b.x, acc[2][0]); acc[2][1] = fmaf(a2, b.y, acc[2][1]);
        acc[2][2] = fmaf(a2, b.z, acc[2][2]); acc[2][3] = fmaf(a2, b.w, acc[2][3]);
        acc[3][0] = fmaf(a3, b.x, acc[3][0]); acc[3][1] = fmaf(a3, b.y, acc[3][1]);
        acc[3][2] = fmaf(a3, b.z, acc[3][2]); acc[3][3] = fmaf(a3, b.w, acc[3][3]);
    }

    // epilogue: pre-relu scatter max into M
    #pragma unroll
    for (int r = 0; r < 4; r++) {
        int gp = p0 + ty * 4 + r;
        int fl = g_flat[gp];
        float* o = g_M + (size_t)fl * 64 + tx * 4;
        #pragma unroll
        for (int c = 0; c < 4; c++) atomicMaxFloat(o + c, acc[r][c]);
    }
}

// ---------------------------------------------------------------------------
// K4: out[v] = relu(M[v] + v1[v] @ W2[64:]) for every voxel (dense write).
// Empty voxels: M=-inf, v1=0 -> relu(-inf)=0 == where(occ,...,0).
// Contiguous voxel rows: coalesced loads/stores, no atomics.
// ---------------------------------------------------------------------------
__global__ __launch_bounds__(256)
void k_vox(const float* __restrict__ W2, float* __restrict__ out) {
    __shared__ float sW[64 * 64];
    __shared__ float sA[64 * SA_LD];

    int tid = threadIdx.x;
    int v0 = blockIdx.x * 64;
    int tx = tid & 15;
    int ty = tid >> 4;

    float acc[4][4];
    #pragma unroll
    for (int r = 0; r < 4; r++)
        #pragma unroll
        for (int c = 0; c < 4; c++) acc[r][c] = 0.f;

    for (int i = tid; i < 4096; i += 256) sW[i] = W2[4096 + i];  // rows 64..127
    {
        int r = tid >> 2, q = tid & 3;
        int v = min(v0 + r, CANVAS - 1);
        const float4* src = (const float4*)(g_v1 + (size_t)v * 64);
        #pragma unroll
        for (int i = 0; i < 4; i++) {
            float4 vv = src[q * 4 + i];
            *(float4*)&sA[r * SA_LD + (q * 4 + i) * 4] = vv;
        }
    }
    __syncthreads();

    #pragma unroll 16
    for (int k = 0; k < 64; k++) {
        float4 b = *(const float4*)&sW[k * 64 + tx * 4];
        float a0 = sA[(ty * 4 + 0) * SA_LD + k];
        float a1 = sA[(ty * 4 + 1) * SA_LD + k];
        float a2 = sA[(ty * 4 + 2) * SA_LD + k];
        float a3 = sA[(ty * 4 + 3) * SA_LD + k];
        acc[0][0] = fmaf(a0, b.x, acc[0][0]); acc[0][1] = fmaf(a0, b.y, acc[0][1]);
        acc[0][2] = fmaf(a0, b.z, acc[0][2]); acc[0][3] = fmaf(a0, b.w, acc[0][3]);
        acc[1][0] = fmaf(a1, b.x, acc[1][0]); acc[1][1] = fmaf(a1, b.y, acc[1][1]);
        acc[1][2] = fmaf(a1, b.z, acc[1][2]); acc[1][3] = fmaf(a1, b.w, acc[1][3]);
        acc[2][0] = fmaf(a2, b.x, acc[2][0]); acc[2][1] = fmaf(a2, b.y, acc[2][1]);
        acc[2][2] = fmaf(a2, b.z, acc[2][2]); acc[2][3] = fmaf(a2, b.w, acc[2][3]);
        acc[3][0] = fmaf(a3, b.x, acc[3][0]); acc[3][1] = fmaf(a3, b.y, acc[3][1]);
        acc[3][2] = fmaf(a3, b.z, acc[3][2]); acc[3][3] = fmaf(a3, b.w, acc[3][3]);
    }

    // epilogue: out = relu(acc + M), dense
    #pragma unroll
    for (int r = 0; r < 4; r++) {
        int v = v0 + ty * 4 + r;
        if (v >= CANVAS) continue;
        float4 m4 = *(const float4*)(g_M + (size_t)v * 64 + tx * 4);
        float4 o;
        o.x = fmaxf(acc[r][0] + m4.x, 0.f);
        o.y = fmaxf(acc[r][1] + m4.y, 0.f);
        o.z = fmaxf(acc[r][2] + m4.z, 0.f);
        o.w = fmaxf(acc[r][3] + m4.w, 0.f);
        *(float4*)(out + (size_t)v * 64 + tx * 4) = o;
    }
}

// ---------------------------------------------------------------------------
extern "C" void kernel_launch(void* const* d_in, const int* in_sizes, int n_in,
                              void* d_out, int out_size) {
    const float* points = (const float*)d_in[0];  // [400000, 5]
    const float* W1     = (const float*)d_in[1];  // [11, 64]
    const float* W2     = (const float*)d_in[2];  // [128, 64]
    float* out = (float*)d_out;                   // [219024, 64]

    k_init<<<8192, 256>>>();
    k_scatter<<<(N_PTS + 255) / 256, 256>>>(points);
    k_pf1<<<N_PTS / 8, 256>>>(points, W1);
    k_pf2a<<<N_PTS / 64, 256>>>(W2);
    k_vox<<<(CANVAS + 63) / 64, 256>>>(W2, out);
}

// round 11
// speedup vs baseline: 1.4223x; 1.0230x over previous
#include <cuda_runtime.h>
#include <cstdint>

#define N_PTS   400000
#define NXY     468
#define CANVAS  (468 * 468)          // 219024
#define VXY     0.32f
#define VZf     6.0f
#define PCMINX  (-74.88f)
#define PCMINY  (-74.88f)
#define PCMINZ  (-2.0f)

// -------- scratch (static device globals; no allocations allowed) ----------
__device__ int   g_flat[N_PTS];
__device__ int   g_cnt[CANVAS];
__device__ float g_vsum[CANVAS * 3];
__device__ float g_v1[CANVAS * 64];             // 56 MB
__device__ float g_M[CANVAS * 64];              // 56 MB  pre-relu segment max

#define NEG_INF_BITS 0xff800000u

// ---------------------------------------------------------------------------
// K0: zero cnt / vsum / v1 ; fill M with -inf.  (out is written densely by k_vox)
// ---------------------------------------------------------------------------
__global__ void k_init() {
    int idx = blockIdx.x * blockDim.x + threadIdx.x;
    int stride = gridDim.x * blockDim.x;
    const int n4 = (CANVAS * 64) / 4;
    float4 z = make_float4(0.f, 0.f, 0.f, 0.f);
    float ninf = __uint_as_float(NEG_INF_BITS);
    float4 nf = make_float4(ninf, ninf, ninf, ninf);
    float4* v4 = (float4*)g_v1;
    float4* m4 = (float4*)g_M;
    for (int i = idx; i < n4; i += stride) {
        v4[i] = z;
        m4[i] = nf;
    }
    for (int i = idx; i < CANVAS; i += stride) {
        g_cnt[i] = 0;
        g_vsum[3 * i + 0] = 0.f;
        g_vsum[3 * i + 1] = 0.f;
        g_vsum[3 * i + 2] = 0.f;
    }
}

// ---------------------------------------------------------------------------
// K1: per-point voxel index + count / xyz-sum scatter
// ---------------------------------------------------------------------------
__device__ __forceinline__ int voxel_coord(float v, float vmin, float vox, int nmax) {
    int c = (int)floorf(__fdiv_rn(v - vmin, vox));
    return min(max(c, 0), nmax - 1);
}

__global__ void k_scatter(const float* __restrict__ pts) {
    int i = blockIdx.x * blockDim.x + threadIdx.x;
    if (i >= N_PTS) return;
    float x = pts[i * 5 + 0];
    float y = pts[i * 5 + 1];
    float z = pts[i * 5 + 2];
    int cx = voxel_coord(x, PCMINX, VXY, NXY);
    int cy = voxel_coord(y, PCMINY, VXY, NXY);
    int flat = cy * NXY + cx;          // NZ==1 -> cz always 0
    g_flat[i] = flat;
    atomicAdd(&g_cnt[flat], 1);
    atomicAdd(&g_vsum[3 * flat + 0], x);
    atomicAdd(&g_vsum[3 * flat + 1], y);
    atomicAdd(&g_vsum[3 * flat + 2], z);
}

// ---------------------------------------------------------------------------
// float atomic max supporting negatives:
// sign>=0 -> int atomicMax; sign<0 -> uint atomicMin.  Init -inf.  Exact.
// ---------------------------------------------------------------------------
__device__ __forceinline__ void atomicMaxFloat(float* addr, float v) {
    int b = __float_as_int(v);
    if (b >= 0) atomicMax((int*)addr, b);
    else        atomicMin((unsigned int*)addr, (unsigned int)b);
}

#define SA_LD 68

// ---------------------------------------------------------------------------
// K2 (fused): per 64-point tile:
//   stage 1: pf1 = relu(features @ W1) computed IN-KERNEL into sA
//            (4 threads/point, 16 channels each) + atomicMax into v1
//   stage 2: s = pf1 @ W2[:64]  (R10-proven 4x4 microkernel, K=64)
//   epilogue: pre-relu scatter atomicMaxFloat into M[flat]
// ---------------------------------------------------------------------------
__global__ __launch_bounds__(256)
void k_fused(const float* __restrict__ pts, const float* __restrict__ W1,
             const float* __restrict__ W2) {
    __shared__ __align__(16) float sW1[11 * 64];
    __shared__ __align__(16) float sW[64 * 64];
    __shared__ __align__(16) float sA[64 * SA_LD];

    int tid = threadIdx.x;
    int p0 = blockIdx.x * 64;          // 6250 * 64 = 400000 exactly
    int tx = tid & 15;
    int ty = tid >> 4;

    for (int i = tid; i < 11 * 64; i += 256) sW1[i] = W1[i];
    for (int i = tid; i < 4096; i += 256) sW[i] = W2[i];   // W2 rows 0..63
    __syncthreads();

    // ---- stage 1: compute pf1 for point pt, channels cg*16 .. cg*16+15
    {
        int pt = tid >> 2;
        int cg = tid & 3;
        int gp = p0 + pt;

        float x  = pts[gp * 5 + 0];
        float y  = pts[gp * 5 + 1];
        float z  = pts[gp * 5 + 2];
        float p3 = pts[gp * 5 + 3];
        float p4 = pts[gp * 5 + 4];

        int flat = g_flat[gp];
        float inv = 1.0f / fmaxf((float)g_cnt[flat], 1.0f);
        float mx = g_vsum[3 * flat + 0] * inv;
        float my = g_vsum[3 * flat + 1] * inv;
        float mz = g_vsum[3 * flat + 2] * inv;

        int cxv = flat % NXY;
        int cyv = flat / NXY;

        float f[11];
        f[0] = x;  f[1] = y;  f[2] = z;  f[3] = p3;  f[4] = p4;
        f[5] = x - mx;  f[6] = y - my;  f[7] = z - mz;
        f[8]  = x - ((float)cxv * VXY + (VXY * 0.5f + PCMINX));
        f[9]  = y - ((float)cyv * VXY + (VXY * 0.5f + PCMINY));
        f[10] = z - (VZf * 0.5f + PCMINZ);

        const float4* w4 = (const float4*)sW1;   // [11][16] float4
        #pragma unroll
        for (int c4 = 0; c4 < 4; c4++) {
            int ch = cg * 16 + c4 * 4;           // channel base
            float a0 = 0.f, a1 = 0.f, a2 = 0.f, a3 = 0.f;
            #pragma unroll
            for (int k = 0; k < 11; k++) {
                float4 w = w4[k * 16 + (ch >> 2)];
                a0 = fmaf(f[k], w.x, a0);
                a1 = fmaf(f[k], w.y, a1);
                a2 = fmaf(f[k], w.z, a2);
                a3 = fmaf(f[k], w.w, a3);
            }
            a0 = fmaxf(a0, 0.f); a1 = fmaxf(a1, 0.f);
            a2 = fmaxf(a2, 0.f); a3 = fmaxf(a3, 0.f);

            float* d = sA + pt * SA_LD + ch;
            d[0] = a0; d[1] = a1; d[2] = a2; d[3] = a3;

            // relu >= 0, v1 zero-init -> int atomicMax exact
            int* vb = (int*)&g_v1[(size_t)flat * 64 + ch];
            if (a0 > 0.f) atomicMax(vb + 0, __float_as_int(a0));
            if (a1 > 0.f) atomicMax(vb + 1, __float_as_int(a1));
            if (a2 > 0.f) atomicMax(vb + 2, __float_as_int(a2));
            if (a3 > 0.f) atomicMax(vb + 3, __float_as_int(a3));
        }
    }
    __syncthreads();

    // ---- stage 2: GEMM s = sA @ sW  (4x4 micro-tile, K=64)
    float acc[4][4];
    #pragma unroll
    for (int r = 0; r < 4; r++)
        #pragma unroll
        for (int c = 0; c < 4; c++) acc[r][c] = 0.f;

    #pragma unroll 16
    for (int k = 0; k < 64; k++) {
        float4 b = *(const float4*)&sW[k * 64 + tx * 4];
        float a0 = sA[(ty * 4 + 0) * SA_LD + k];
        float a1 = sA[(ty * 4 + 1) * SA_LD + k];
        float a2 = sA[(ty * 4 + 2) * SA_LD + k];
        float a3 = sA[(ty * 4 + 3) * SA_LD + k];
        acc[0][0] = fmaf(a0, b.x, acc[0][0]); acc[0][1] = fmaf(a0, b.y, acc[0][1]);
        acc[0][2] = fmaf(a0, b.z, acc[0][2]); acc[0][3] = fmaf(a0, b.w, acc[0][3]);
        acc[1][0] = fmaf(a1, b.x, acc[1][0]); acc[1][1] = fmaf(a1, b.y, acc[1][1]);
        acc[1][2] = fmaf(a1, b.z, acc[1][2]); acc[1][3] = fmaf(a1, b.w, acc[1][3]);
        acc[2][0] = fmaf(a2, b.x, acc[2][0]); acc[2][1] = fmaf(a2, b.y, acc[2][1]);
        acc[2][2] = fmaf(a2, b.z, acc[2][2]); acc[2][3] = fmaf(a2, b.w, acc[2][3]);
        acc[3][0] = fmaf(a3, b.x, acc[3][0]); acc[3][1] = fmaf(a3, b.y, acc[3][1]);
        acc[3][2] = fmaf(a3, b.z, acc[3][2]); acc[3][3] = fmaf(a3, b.w, acc[3][3]);
    }

    // ---- epilogue: pre-relu scatter max into M
    #pragma unroll
    for (int r = 0; r < 4; r++) {
        int gp = p0 + ty * 4 + r;
        int fl = g_flat[gp];
        float* o = g_M + (size_t)fl * 64 + tx * 4;
        #pragma unroll
        for (int c = 0; c < 4; c++) atomicMaxFloat(o + c, acc[r][c]);
    }
}

// ---------------------------------------------------------------------------
// K3: out[v] = relu(M[v] + v1[v] @ W2[64:]) for every voxel (dense write).
// Empty voxels: M=-inf, v1=0 -> relu(-inf+0)=0 == where(occ,...,0).
// ---------------------------------------------------------------------------
__global__ __launch_bounds__(256)
void k_vox(const float* __restrict__ W2, float* __restrict__ out) {
    __shared__ __align__(16) float sW[64 * 64];
    __shared__ __align__(16) float sA[64 * SA_LD];

    int tid = threadIdx.x;
    int v0 = blockIdx.x * 64;
    int tx = tid & 15;
    int ty = tid >> 4;

    float acc[4][4];
    #pragma unroll
    for (int r = 0; r < 4; r++)
        #pragma unroll
        for (int c = 0; c < 4; c++) acc[r][c] = 0.f;

    for (int i = tid; i < 4096; i += 256) sW[i] = W2[4096 + i];  // rows 64..127
    {
        int r = tid >> 2, q = tid & 3;
        int v = min(v0 + r, CANVAS - 1);
        const float4* src = (const float4*)(g_v1 + (size_t)v * 64);
        #pragma unroll
        for (int i = 0; i < 4; i++) {
            float4 vv = src[q * 4 + i];
            *(float4*)&sA[r * SA_LD + (q * 4 + i) * 4] = vv;
        }
    }
    __syncthreads();

    #pragma unroll 16
    for (int k = 0; k < 64; k++) {
        float4 b = *(const float4*)&sW[k * 64 + tx * 4];
        float a0 = sA[(ty * 4 + 0) * SA_LD + k];
        float a1 = sA[(ty * 4 + 1) * SA_LD + k];
        float a2 = sA[(ty * 4 + 2) * SA_LD + k];
        float a3 = sA[(ty * 4 + 3) * SA_LD + k];
        acc[0][0] = fmaf(a0, b.x, acc[0][0]); acc[0][1] = fmaf(a0, b.y, acc[0][1]);
        acc[0][2] = fmaf(a0, b.z, acc[0][2]); acc[0][3] = fmaf(a0, b.w, acc[0][3]);
        acc[1][0] = fmaf(a1, b.x, acc[1][0]); acc[1][1] = fmaf(a1, b.y, acc[1][1]);
        acc[1][2] = fmaf(a1, b.z, acc[1][2]); acc[1][3] = fmaf(a1, b.w, acc[1][3]);
        acc[2][0] = fmaf(a2, b.x, acc[2][0]); acc[2][1] = fmaf(a2, b.y, acc[2][1]);
        acc[2][2] = fmaf(a2, b.z, acc[2][2]); acc[2][3] = fmaf(a2, b.w, acc[2][3]);
        acc[3][0] = fmaf(a3, b.x, acc[3][0]); acc[3][1] = fmaf(a3, b.y, acc[3][1]);
        acc[3][2] = fmaf(a3, b.z, acc[3][2]); acc[3][3] = fmaf(a3, b.w, acc[3][3]);
    }

    // epilogue: out = relu(acc + M), dense coalesced
    #pragma unroll
    for (int r = 0; r < 4; r++) {
        int v = v0 + ty * 4 + r;
        if (v >= CANVAS) continue;
        float4 m4 = *(const float4*)(g_M + (size_t)v * 64 + tx * 4);
        float4 o;
        o.x = fmaxf(acc[r][0] + m4.x, 0.f);
        o.y = fmaxf(acc[r][1] + m4.y, 0.f);
        o.z = fmaxf(acc[r][2] + m4.z, 0.f);
        o.w = fmaxf(acc[r][3] + m4.w, 0.f);
        *(float4*)(out + (size_t)v * 64 + tx * 4) = o;
    }
}

// ---------------------------------------------------------------------------
extern "C" void kernel_launch(void* const* d_in, const int* in_sizes, int n_in,
                              void* d_out, int out_size) {
    const float* points = (const float*)d_in[0];  // [400000, 5]
    const float* W1     = (const float*)d_in[1];  // [11, 64]
    const float* W2     = (const float*)d_in[2];  // [128, 64]
    float* out = (float*)d_out;                   // [219024, 64]

    k_init<<<8192, 256>>>();
    k_scatter<<<(N_PTS + 255) / 256, 256>>>(points);
    k_fused<<<N_PTS / 64, 256>>>(points, W1, W2);
    k_vox<<<(CANVAS + 63) / 64, 256>>>(W2, out);
}